// round 12
// baseline (speedup 1.0000x reference)
#include <cuda_runtime.h>
#include <cstdint>

// x: (B=8, H=256, W=256, C=64) fp32, WIN=16, half=8
// out: (B, 961, 16*16*64) fp32, partitions (0,0),(0,8),(8,0),(8,8)
//      = 256, 240(15 cols), 240(16 cols), 225 windows per batch.
//
// Read-once / scatter-x4: one CTA per ALIGNED 16x16 input tile (b, wr, wc).
// Loads the 64KB tile once (16 coalesced 4KB rows, front-batched LDG.128),
// then stores each float4 to all 4 partition outputs it belongs to:
//   P00: window (wr,wc), same (r,p)
//   P0h: window (wr, wc-1+(p>=8)), col (p+8)&15        [skip at col edges]
//   Ph0: window (wr-1+(r>=8), wc), row (r+8)&15        [skip at row edges]
//   Phh: both shifts                                    [skip at either edge]
// Cuts L2 read traffic 4x (537MB -> 134MB); writes unchanged (504MB, .cs).

#define NPB 961
#define ROW_F4 4096            // float4 per input image row (256*64/4)
#define WIN_F4 4096            // float4 per output window (16*16*64/4)

__global__ void __launch_bounds__(256, 2)
partition_kernel(const float4* __restrict__ x, float4* __restrict__ out)
{
    const int blk  = blockIdx.x;        // b*256 + wr*16 + wc
    const int b    = blk >> 8;
    const int tile = blk & 255;
    const int wr   = tile >> 4;
    const int wc   = tile & 15;

    const int t = threadIdx.x;          // float4 index within a 4KB tile row
    const int p = t >> 4;               // pixel (column) 0..15
    const int q = t & 15;               // float4 within pixel's 64 channels

    const float4* __restrict__ src =
        x + (size_t)(b * 256 + wr * 16) * ROW_F4 + (size_t)wc * 256;

    // ---- destinations ----
    const size_t base = (size_t)b * NPB;
    const int  ph   = (p + 8) & 15;
    const bool v0h  = (p < 8) ? (wc >= 1) : (wc <= 14);
    const int  wch  = wc - 1 + (p >= 8);
    const bool vlo  = (wr >= 1);        // for r<8 row-shifted targets
    const bool vhi  = (wr <= 14);       // for r>=8 row-shifted targets

    float4* d00 = out + (base + (size_t)(wr * 16 + wc)) * WIN_F4;
    float4* d0h = out + (base + 256 + (size_t)(wr * 15 + wch)) * WIN_F4;
    float4* dh0_lo = out + (base + 496 + (size_t)((wr - 1) * 16 + wc)) * WIN_F4;
    float4* dh0_hi = out + (base + 496 + (size_t)(wr * 16 + wc)) * WIN_F4;
    float4* dhh_lo = out + (base + 736 + (size_t)((wr - 1) * 15 + wch)) * WIN_F4;
    float4* dhh_hi = out + (base + 736 + (size_t)(wr * 15 + wch)) * WIN_F4;

    // ---- load the whole tile: 16 front-batched coalesced LDG.128 ----
    float4 v[16];
#pragma unroll
    for (int r = 0; r < 16; ++r)
        v[r] = __ldg(&src[(size_t)r * ROW_F4 + t]);

    // ---- scatter: up to 4 streaming stores per element ----
#pragma unroll
    for (int r = 0; r < 16; ++r) {
        const int rh = (r + 8) & 15;
        __stcs(&d00[r * 256 + t], v[r]);
        if (v0h)
            __stcs(&d0h[r * 256 + ph * 16 + q], v[r]);
        if (r < 8) {
            if (vlo)        __stcs(&dh0_lo[rh * 256 + t], v[r]);
            if (vlo && v0h) __stcs(&dhh_lo[rh * 256 + ph * 16 + q], v[r]);
        } else {
            if (vhi)        __stcs(&dh0_hi[rh * 256 + t], v[r]);
            if (vhi && v0h) __stcs(&dhh_hi[rh * 256 + ph * 16 + q], v[r]);
        }
    }
}

extern "C" void kernel_launch(void* const* d_in, const int* in_sizes, int n_in,
                              void* d_out, int out_size)
{
    const float4* x = (const float4*)d_in[0];
    float4* out = (float4*)d_out;
    partition_kernel<<<8 * 256, 256>>>(x, out);
}

// round 13
// speedup vs baseline: 1.0277x; 1.0277x over previous
#include <cuda_runtime.h>
#include <cstdint>

// x: (B=8, H=256, W=256, C=64) fp32, WIN=16, half=8
// out: (B, 961, 16*16*64) fp32, partition order (0,0),(0,8),(8,0),(8,8)
// windows per partition: 256, 240, 240, 225 -> 961 per batch
//
// R2 skeleton (best: 94.944us): one block per window, 256 threads,
// 16 front-batched LDG.128, launch_bounds(256,2) -> 72 regs, MLP~16.
// A/B experiment: plain evict-normal stores instead of __stcs. Evict-first
// forces eager small write-backs; evict-normal lets L2 accumulate longer
// contiguous dirty spans for the DRAM scheduler (write = 87% of traffic).

#define Hh 256
#define Ww 256
#define Cc 64
#define NPB 961                // windows per batch
#define ROW_F4 (Ww * Cc / 4)   // float4 per input image row = 4096

__global__ void __launch_bounds__(256, 2)
partition_kernel(const float* __restrict__ x, float* __restrict__ out)
{
    const int blk = blockIdx.x;            // b * 961 + p
    const int b   = blk / NPB;
    const int p   = blk - b * NPB;

    int r0, c0, nc, base;
    if (p < 256)      { r0 = 0; c0 = 0; nc = 16; base = 0;   }
    else if (p < 496) { r0 = 0; c0 = 8; nc = 15; base = 256; }
    else if (p < 736) { r0 = 8; c0 = 0; nc = 16; base = 496; }
    else              { r0 = 8; c0 = 8; nc = 15; base = 736; }

    const int q  = p - base;
    const int wr = q / nc;
    const int wc = q - wr * nc;
    const int row0 = r0 + wr * 16;
    const int col0 = c0 + wc * 16;

    const float4* __restrict__ src =
        reinterpret_cast<const float4*>(x) +
        (size_t)(b * Hh + row0) * ROW_F4 + (size_t)col0 * (Cc / 4);
    float4* __restrict__ dst =
        reinterpret_cast<float4*>(out) + (size_t)blk * (16 * 16 * Cc / 4);

    const int t = threadIdx.x;             // 0..255: one float4 of the 4KB row

    // Front-batch ALL 16 independent LDG.128s, then drain with 16
    // plain (evict-normal) STG.128s.
    float4 v[16];
#pragma unroll
    for (int i = 0; i < 16; ++i)
        v[i] = __ldg(&src[(size_t)i * ROW_F4 + t]);
#pragma unroll
    for (int i = 0; i < 16; ++i)
        dst[i * 256 + t] = v[i];
}

extern "C" void kernel_launch(void* const* d_in, const int* in_sizes, int n_in,
                              void* d_out, int out_size)
{
    const float* x = (const float*)d_in[0];
    float* out = (float*)d_out;
    const int nblocks = 8 * NPB;           // 7688
    partition_kernel<<<nblocks, 256>>>(x, out);
}

// round 14
// speedup vs baseline: 1.0647x; 1.0361x over previous
#include <cuda_runtime.h>
#include <cstdint>

// x: (B=8, H=256, W=256, C=64) fp32, WIN=16, half=8
// out: (B, 961, 16*16*64) fp32, partition order (0,0),(0,8),(8,0),(8,8)
// windows per partition: 256, 240, 240, 225 -> 961 per batch
//
// R2 skeleton (best: 94.944us): one block per window, 256 threads,
// 16 front-batched 128-bit loads + 16 streaming (.cs) 128-bit stores,
// launch_bounds(256,2) -> 72 regs, per-thread MLP ~16.
// Final A/B: ld.global.cg (L2-only, no L1 allocation) instead of __ldg(.nc).
// Input lines have ZERO L1 reuse (each 128B line consumed once, coalesced),
// so L1 allocation is pure overhead on a 62%-busy L1tex unit shared with
// the store stream.

#define Hh 256
#define Ww 256
#define Cc 64
#define NPB 961                // windows per batch
#define ROW_F4 (Ww * Cc / 4)   // float4 per input image row = 4096

__global__ void __launch_bounds__(256, 2)
partition_kernel(const float* __restrict__ x, float* __restrict__ out)
{
    const int blk = blockIdx.x;            // b * 961 + p
    const int b   = blk / NPB;
    const int p   = blk - b * NPB;

    int r0, c0, nc, base;
    if (p < 256)      { r0 = 0; c0 = 0; nc = 16; base = 0;   }
    else if (p < 496) { r0 = 0; c0 = 8; nc = 15; base = 256; }
    else if (p < 736) { r0 = 8; c0 = 0; nc = 16; base = 496; }
    else              { r0 = 8; c0 = 8; nc = 15; base = 736; }

    const int q  = p - base;
    const int wr = q / nc;
    const int wc = q - wr * nc;
    const int row0 = r0 + wr * 16;
    const int col0 = c0 + wc * 16;

    const float4* __restrict__ src =
        reinterpret_cast<const float4*>(x) +
        (size_t)(b * Hh + row0) * ROW_F4 + (size_t)col0 * (Cc / 4);
    float4* __restrict__ dst =
        reinterpret_cast<float4*>(out) + (size_t)blk * (16 * 16 * Cc / 4);

    const int t = threadIdx.x;             // 0..255: one float4 of the 4KB row

    // Front-batch ALL 16 independent LDG.128.CG (L2-only), then drain with
    // 16 streaming STG.128.CS.
    float4 v[16];
#pragma unroll
    for (int i = 0; i < 16; ++i) {
        const float4* g = &src[(size_t)i * ROW_F4 + t];
        asm volatile(
            "ld.global.cg.v4.f32 {%0,%1,%2,%3}, [%4];"
            : "=f"(v[i].x), "=f"(v[i].y), "=f"(v[i].z), "=f"(v[i].w)
            : "l"(g));
    }
#pragma unroll
    for (int i = 0; i < 16; ++i)
        __stcs(&dst[i * 256 + t], v[i]);
}

extern "C" void kernel_launch(void* const* d_in, const int* in_sizes, int n_in,
                              void* d_out, int out_size)
{
    const float* x = (const float*)d_in[0];
    float* out = (float*)d_out;
    const int nblocks = 8 * NPB;           // 7688
    partition_kernel<<<nblocks, 256>>>(x, out);
}

// round 15
// speedup vs baseline: 1.0676x; 1.0027x over previous
#include <cuda_runtime.h>
#include <cstdint>

// x: (B=8, H=256, W=256, C=64) fp32, WIN=16, half=8
// out: (B, 961, 16*16*64) fp32, partition order (0,0),(0,8),(8,0),(8,8)
// windows per partition: 256, 240, 240, 225 -> 961 per batch
//
// Deepest-MLP point of the R2 family: one block per window, 128 threads,
// each thread owns 32 float4 (two per window-row: rows i, columns
// {t, t+128}). All 32 loads front-batched (128 data regs), then 32
// streaming stores. launch_bounds(128,3) -> <=85? no: cap 168 regs/thread
// budget (128*168*3 = 64.5k) — ptxas target ~150. Fewer warps (12/SM),
// 2-4x deeper per-warp request queue than R2.

#define Hh 256
#define Ww 256
#define Cc 64
#define NPB 961                // windows per batch
#define ROW_F4 (Ww * Cc / 4)   // float4 per input image row = 4096

__global__ void __launch_bounds__(128, 3)
partition_kernel(const float* __restrict__ x, float* __restrict__ out)
{
    const int blk = blockIdx.x;            // b * 961 + p
    const int b   = blk / NPB;
    const int p   = blk - b * NPB;

    int r0, c0, nc, base;
    if (p < 256)      { r0 = 0; c0 = 0; nc = 16; base = 0;   }
    else if (p < 496) { r0 = 0; c0 = 8; nc = 15; base = 256; }
    else if (p < 736) { r0 = 8; c0 = 0; nc = 16; base = 496; }
    else              { r0 = 8; c0 = 8; nc = 15; base = 736; }

    const int q  = p - base;
    const int wr = q / nc;
    const int wc = q - wr * nc;
    const int row0 = r0 + wr * 16;
    const int col0 = c0 + wc * 16;

    const float4* __restrict__ src =
        reinterpret_cast<const float4*>(x) +
        (size_t)(b * Hh + row0) * ROW_F4 + (size_t)col0 * (Cc / 4);
    float4* __restrict__ dst =
        reinterpret_cast<float4*>(out) + (size_t)blk * (16 * 16 * Cc / 4);

    const int t = threadIdx.x;             // 0..127

    // 32 independent 128-bit loads per thread: row i, float4 {t, t+128}.
    float4 v[32];
#pragma unroll
    for (int i = 0; i < 16; ++i) {
        v[2 * i]     = __ldg(&src[(size_t)i * ROW_F4 + t]);
        v[2 * i + 1] = __ldg(&src[(size_t)i * ROW_F4 + t + 128]);
    }
#pragma unroll
    for (int i = 0; i < 16; ++i) {
        __stcs(&dst[i * 256 + t],       v[2 * i]);
        __stcs(&dst[i * 256 + t + 128], v[2 * i + 1]);
    }
}

extern "C" void kernel_launch(void* const* d_in, const int* in_sizes, int n_in,
                              void* d_out, int out_size)
{
    const float* x = (const float*)d_in[0];
    float* out = (float*)d_out;
    const int nblocks = 8 * NPB;           // 7688
    partition_kernel<<<nblocks, 128>>>(x, out);
}